// round 5
// baseline (speedup 1.0000x reference)
#include <cuda_runtime.h>

#define NB   16384
#define NH   1024
#define NIN  32
#define NU   10
#define MI   138
#define ITER 30
#define SIGMA 0.1f
#define FC1_BLOCKS (NB/128)   // 128
#define FC2_BLOCKS (NB/8)     // 2048

#define IPB  32               // items per IPM block (128 threads, 4 per item)
#define SROW 129              // stride ≡ 1 mod 32 -> conflict-free quad access

typedef unsigned long long u64;

// ---------------- device scratch (static, no allocs) ----------------
__device__ float g_h1[NB*NH];              // 64 MB
__device__ float g_bn1p[FC1_BLOCKS*NH];
__device__ float g_bn1q[FC1_BLOCKS*NH];
__device__ float g_W2f[NU*NH];
__device__ float g_b2f[NU];
__device__ float g_t2[NB*NU];
__device__ float g_bn2p[FC2_BLOCKS*NU];
__device__ float g_bn2q[FC2_BLOCKS*NU];
__device__ float g_bn2ac[2*NU];
__device__ float g_Qhat[NU*NU];
__device__ float g_G[MI*NU];
__device__ float g_h[MI];

__device__ __forceinline__ float frcp(float x){ float r; asm("rcp.approx.f32 %0, %1;" : "=f"(r) : "f"(x)); return r; }
__device__ __forceinline__ float lrelu(float v){ return v > 0.f ? v : 0.2f*v; }

// ---- packed f32x2 helpers ----
__device__ __forceinline__ u64 pk(float x, float y){
    u64 r; asm("mov.b64 %0, {%1,%2};" : "=l"(r) : "f"(x), "f"(y)); return r;
}
__device__ __forceinline__ void upk(u64 v, float& x, float& y){
    asm("mov.b64 {%0,%1}, %2;" : "=f"(x), "=f"(y) : "l"(v));
}
__device__ __forceinline__ u64 fma2(u64 a, u64 b, u64 c){
    u64 d; asm("fma.rn.f32x2 %0, %1, %2, %3;" : "=l"(d) : "l"(a), "l"(b), "l"(c)); return d;
}
__device__ __forceinline__ u64 add2(u64 a, u64 b){
    u64 d; asm("add.rn.f32x2 %0, %1, %2;" : "=l"(d) : "l"(a), "l"(b)); return d;
}
__device__ __forceinline__ u64 sh64(u64 v, int m){
    return __shfl_xor_sync(0xffffffffu, v, m);
}

// ---------------- K0: build QP (Q_hat, G, h) -- one block ----------------
__global__ void build_qp(const float* __restrict__ L, const float* __restrict__ LP,
                         const float* __restrict__ LR, const float* __restrict__ A,
                         const float* __restrict__ Bm, const float* __restrict__ u0,
                         const float* __restrict__ s0)
{
    __shared__ float Q[32*32], P[32*32], R[4], pw[4][64], Bh[128*NU], Ms[128*NU];
    const int t = threadIdx.x; // 256 threads

    for (int e = t; e < 1024; e += 256){
        int i = e >> 5, j = e & 31;
        int kmax = i < j ? i : j;
        float aq = (i==j) ? 1e-4f : 0.f;
        float ap = aq;
        for (int k = 0; k <= kmax; k++){
            aq = fmaf(L [i*32+k], L [j*32+k], aq);
            ap = fmaf(LP[i*32+k], LP[j*32+k], ap);
        }
        Q[e] = aq; P[e] = ap;
    }
    if (t < 4){
        int i = t >> 1, j = t & 1;
        int kmax = i < j ? i : j;
        float a = (i==j) ? 1e-4f : 0.f;
        for (int k = 0; k <= kmax; k++) a = fmaf(LR[i*2+k], LR[j*2+k], a);
        R[t] = a;
    }
    if (t < 64) pw[0][t] = Bm[t];
    __syncthreads();
    for (int s = 1; s < 4; s++){
        if (t < 64){
            int r = t >> 1, c = t & 1;
            float acc = 0.f;
            for (int k = 0; k < 32; k++) acc = fmaf(A[r*32+k], pw[s-1][k*2+c], acc);
            pw[s][t] = acc;
        }
        __syncthreads();
    }
    for (int e = t; e < 128*NU; e += 256){
        int row = e / NU, col = e - row*NU;
        int bi = row >> 5, r = row & 31, bj = col >> 1, c = col & 1;
        Bh[e] = (bj <= bi) ? pw[bi-bj][r*2+c] : 0.f;
    }
    __syncthreads();
    for (int e = t; e < 128*NU; e += 256){
        int row = e / NU, col = e - row*NU;
        int b = row >> 5, r = row & 31;
        const float* Qb = (b < 3) ? Q : P;
        float acc = 0.f;
        for (int k = 0; k < 32; k++) acc = fmaf(Qb[r*32+k], Bh[(b*32+k)*NU+col], acc);
        Ms[e] = acc;
    }
    __syncthreads();
    if (t < 100){
        int a = t / NU, b = t - (t/NU)*NU;
        float acc = ((a>>1) == (b>>1)) ? R[(a&1)*2+(b&1)] : 0.f;
        for (int row = 0; row < 128; row++) acc = fmaf(Bh[row*NU+a], Ms[row*NU+b], acc);
        g_Qhat[t] = acc;
    }
    for (int e = t; e < MI*NU; e += 256){
        int row = e / NU, col = e - (e/NU)*NU;
        g_G[e] = (row < NU) ? ((row==col) ? 1.f : 0.f) : Bh[(row-NU)*NU+col];
    }
    if (t < MI){
        float acc = s0[t];
        if (t < NU) acc += u0[t];
        else { for (int j = 0; j < NU; j++) acc = fmaf(Bh[(t-NU)*NU+j], u0[j], acc); }
        g_h[t] = acc;
    }
}

// ---------------- K1: fc1 + leaky_relu + bn1 partial stats ----------------
__global__ void __launch_bounds__(256) fc1_kernel(const float* __restrict__ x,
    const float* __restrict__ W1, const float* __restrict__ b1)
{
    __shared__ __align__(16) float xs[128*32];
    const int t = threadIdx.x;
    const int row0 = blockIdx.x * 128;
    {
        const float4* src = (const float4*)(x + row0*32);
        float4* dst = (float4*)xs;
        for (int e = t; e < 1024; e += 256) dst[e] = src[e];
    }
    __syncthreads();
    #pragma unroll
    for (int ff = 0; ff < 4; ff++){
        const int f = t + ff*256;
        float w[32];
        const float4* wp = (const float4*)(W1 + f*32);
        #pragma unroll
        for (int k = 0; k < 8; k++){
            float4 v = wp[k];
            w[4*k+0]=v.x; w[4*k+1]=v.y; w[4*k+2]=v.z; w[4*k+3]=v.w;
        }
        const float bias = b1[f];
        float sum = 0.f, sq = 0.f;
        for (int r = 0; r < 128; r++){
            float acc = bias;
            const float4* xp = (const float4*)(xs + r*32);
            #pragma unroll
            for (int k = 0; k < 8; k++){
                float4 xv = xp[k];
                acc = fmaf(xv.x, w[4*k+0], acc);
                acc = fmaf(xv.y, w[4*k+1], acc);
                acc = fmaf(xv.z, w[4*k+2], acc);
                acc = fmaf(xv.w, w[4*k+3], acc);
            }
            float v = lrelu(acc);
            g_h1[(row0+r)*NH + f] = v;
            sum += v; sq = fmaf(v, v, sq);
        }
        g_bn1p[blockIdx.x*NH + f] = sum;
        g_bn1q[blockIdx.x*NH + f] = sq;
    }
}

// ---------------- K2: bn1 finalize fused with fc2-weight fold ----------------
__global__ void fold_all(const float* __restrict__ W2, const float* __restrict__ b2,
                         const float* __restrict__ g1, const float* __restrict__ beta1)
{
    __shared__ float red[256];
    const int u = blockIdx.x, t = threadIdx.x;
    float dot = 0.f;
    for (int k = t; k < NH; k += 256){
        float sum = 0.f, sq = 0.f;
        for (int b = 0; b < FC1_BLOCKS; b++){
            sum += g_bn1p[b*NH + k];
            sq  += g_bn1q[b*NH + k];
        }
        float mu  = sum * (1.f/(float)NB);
        float var = sq  * (1.f/(float)NB) - mu*mu;
        float a = g1[k]*rsqrtf(var + 1e-5f);
        float c = beta1[k] - mu*a;
        float wv = W2[u*NH + k];
        g_W2f[u*NH + k] = wv * a;
        dot = fmaf(wv, c, dot);
    }
    red[t] = dot; __syncthreads();
    for (int s = 128; s > 0; s >>= 1){
        if (t < s) red[t] += red[t+s];
        __syncthreads();
    }
    if (t == 0) g_b2f[u] = b2[u] + red[0];
}

// ---------------- K3: fc2 + leaky_relu + bn2 partial stats ----------------
__global__ void __launch_bounds__(256) fc2_kernel()
{
    __shared__ float Ws[NU*NH];
    __shared__ float bs[NU];
    __shared__ float wt2[8][NU];
    const int t = threadIdx.x, lane = t & 31, wid = t >> 5;
    for (int e = t; e < NU*NH; e += 256) Ws[e] = g_W2f[e];
    if (t < NU) bs[t] = g_b2f[t];
    __syncthreads();
    const int item = blockIdx.x*8 + wid;
    float acc[NU];
    #pragma unroll
    for (int u = 0; u < NU; u++) acc[u] = 0.f;
    const float* hrow = g_h1 + item*NH;
    for (int j = 0; j < 32; j++){
        float hv = hrow[j*32 + lane];
        #pragma unroll
        for (int u = 0; u < NU; u++) acc[u] = fmaf(hv, Ws[u*NH + j*32 + lane], acc[u]);
    }
    #pragma unroll
    for (int u = 0; u < NU; u++){
        #pragma unroll
        for (int off = 16; off > 0; off >>= 1)
            acc[u] += __shfl_xor_sync(0xffffffffu, acc[u], off);
    }
    if (lane == 0){
        #pragma unroll
        for (int u = 0; u < NU; u++){
            float v = lrelu(acc[u] + bs[u]);
            g_t2[item*NU + u] = v;
            wt2[wid][u] = v;
        }
    }
    __syncthreads();
    if (t < NU){
        float s = 0.f, q = 0.f;
        #pragma unroll
        for (int w = 0; w < 8; w++){ float v = wt2[w][t]; s += v; q = fmaf(v, v, q); }
        g_bn2p[blockIdx.x*NU + t] = s;
        g_bn2q[blockIdx.x*NU + t] = q;
    }
}

// ---------------- K4: finalize bn2 ----------------
__global__ void bn2_fin(const float* __restrict__ g2, const float* __restrict__ beta2)
{
    __shared__ float red[256*20];
    const int t = threadIdx.x;
    float loc[20];
    #pragma unroll
    for (int j = 0; j < 20; j++) loc[j] = 0.f;
    for (int b = t; b < FC2_BLOCKS; b += 256){
        #pragma unroll
        for (int u = 0; u < NU; u++){
            loc[u]    += g_bn2p[b*NU + u];
            loc[10+u] += g_bn2q[b*NU + u];
        }
    }
    #pragma unroll
    for (int j = 0; j < 20; j++) red[t*20 + j] = loc[j];
    __syncthreads();
    for (int s = 128; s > 0; s >>= 1){
        if (t < s){
            #pragma unroll
            for (int j = 0; j < 20; j++) red[t*20 + j] += red[(t+s)*20 + j];
        }
        __syncthreads();
    }
    if (t < NU){
        float mu  = red[t]    * (1.f/(float)NB);
        float var = red[10+t] * (1.f/(float)NB) - mu*mu;
        float a = g2[t]*rsqrtf(var + 1e-5f);
        g_bn2ac[t]      = a;
        g_bn2ac[NU + t] = beta2[t] - mu*a;
    }
}

// ---------------- K5: batched IPM, one item per THREAD QUAD ----------------
template<int K>
__device__ __forceinline__ void passA_blk(const float* __restrict__ Gblk, int sa0, int hBase,
    const u64* z2, float* Hs, u64* b1p, float smu,
    const float* s_sh, const float* l_sh, float* r_sh, const float* h_sh)
{
    const int KH = K/2;
    #pragma unroll
    for (int j = 0; j < 8; j++){
        const int sa = sa0 + j;
        float sm = s_sh[sa], lm = l_sh[sa];
        float ivs = frcp(sm);
        float w = lm*ivs;
        float g[K]; u64 g2[KH];
        #pragma unroll
        for (int jj = 0; jj < KH; jj++){
            float2 gv = *(const float2*)&Gblk[j*K + 2*jj];
            g[2*jj] = gv.x; g[2*jj+1] = gv.y;
            g2[jj] = pk(gv.x, gv.y);
        }
        u64 acc = pk(0.f, 0.f);
        #pragma unroll
        for (int jj = 0; jj < KH; jj++) acc = fma2(g2[jj], z2[jj], acc);
        float gx, gy; upk(acc, gx, gy);
        float rp = (gx + gy) + sm - h_sh[hBase + j];
        r_sh[sa] = rp;
        float coef = fmaf(lm, rp, smu)*ivs;
        u64 c2 = pk(coef, coef);
        #pragma unroll
        for (int jj = 0; jj < KH; jj++) b1p[jj] = fma2(c2, g2[jj], b1p[jj]);
        float wg[K];
        #pragma unroll
        for (int a = 0; a < K; a++) wg[a] = w*g[a];
        #pragma unroll
        for (int a = 0; a < K; a++){
            #pragma unroll
            for (int b = 0; b <= a; b++)
                Hs[(a*(a+1))/2+b] = fmaf(g[a], wg[b], Hs[(a*(a+1))/2+b]);
        }
    }
}

template<int K>
__device__ __forceinline__ void passB1_blk(const float* __restrict__ Gblk, int sa0,
    const u64* dz2, float smu, float& q,
    const float* s_sh, const float* l_sh, float* r_sh)
{
    const int KH = K/2;
    #pragma unroll
    for (int j = 0; j < 8; j++){
        const int sa = sa0 + j;
        float sm = s_sh[sa], lm = l_sh[sa];
        float rp = r_sh[sa];
        u64 acc = pk(0.f, 0.f);
        #pragma unroll
        for (int jj = 0; jj < KH; jj++){
            float2 gvj = *(const float2*)&Gblk[j*K + 2*jj];
            acc = fma2(pk(gvj.x, gvj.y), dz2[jj], acc);
        }
        float gx, gy; upk(acc, gx, gy);
        float ds = -(rp + gx + gy);
        float rc = fmaf(sm, lm, -smu);
        float ivs = frcp(sm), ivl = frcp(lm);
        float dlam = -fmaf(lm, ds, rc)*ivs;
        q = fmaxf(q, fmaxf(-ds*ivs, -dlam*ivl));
        r_sh[sa] = ds;
    }
}

__global__ void __launch_bounds__(128, 3) ipm_kernel(float* __restrict__ out)
{
    extern __shared__ float dyn[];
    float* s_sh = dyn;                    // IPB*SROW
    float* l_sh = dyn +   IPB*SROW;
    float* r_sh = dyn + 2*IPB*SROW;
    __shared__ __align__(8) float G_sh[896];
    __shared__ float h_sh[MI];
    __shared__ __align__(8) float Q_sh[NU*NU];
    __shared__ float ac_sh[2*NU];
    // sub-block offsets: GOFF[bi][r] ≡ 8r (mod 32)
    const int GOFF[4][4] = {{0,40,80,120},{160,200,240,280},{320,392,464,536},{608,680,752,824}};

    const int tid = threadIdx.x;
    const int r = tid & 3, q = tid >> 2;
    const int item = blockIdx.x*IPB + q;

    // load packed G: one structured row per thread
    {
        int mm = tid;  // 0..127
        int bi = mm >> 5, lr = mm & 31, rr = lr >> 3, j = lr & 7, K = 2*bi + 2;
        int base = GOFF[bi][rr] + j*K;
        for (int c = 0; c < K; c++) G_sh[base + c] = g_G[(10+mm)*NU + c];
    }
    for (int i = tid; i < MI; i += 128) h_sh[i] = g_h[i];
    if (tid < 100) Q_sh[tid] = g_Qhat[tid];
    if (tid < 20)  ac_sh[tid] = g_bn2ac[tid];
    __syncthreads();

    float p[NU];
    u64 z2[5];
    #pragma unroll
    for (int u = 0; u < NU; u++)
        p[u] = fmaf(g_t2[item*NU+u], ac_sh[u], ac_sh[NU+u]);
    #pragma unroll
    for (int j = 0; j < 5; j++) z2[j] = pk(0.f, 0.f);

    float s_id[NU], l_id[NU];
    #pragma unroll
    for (int m = 0; m < NU; m++){ s_id[m] = 1.f; l_id[m] = 1.f; }

    // this thread's rows: block bi rows mm = 32*bi + 8*r + j
    int saB[4], hB[4];
    const float* Gb[4];
    #pragma unroll
    for (int bi = 0; bi < 4; bi++){
        int mm0 = 32*bi + 8*r;
        saB[bi] = q*SROW + mm0;
        hB[bi]  = 10 + mm0;
        Gb[bi]  = &G_sh[GOFF[bi][r]];
        #pragma unroll
        for (int j = 0; j < 8; j++){
            s_sh[saB[bi]+j] = 1.f; l_sh[saB[bi]+j] = 1.f;
        }
    }
    float musum = (float)MI;   // s=lam=1 initially

    for (int it = 0; it < ITER; it++){
        float smu = musum * (SIGMA/(float)MI);
        // ---- pass A: partial Hs/b1p over this thread's 32 rows ----
        float Hs[55];
        u64 b1p[5];
        #pragma unroll
        for (int e = 0; e < 55; e++) Hs[e] = 0.f;
        #pragma unroll
        for (int j = 0; j < 5; j++) b1p[j] = pk(0.f, 0.f);

        passA_blk<2>(Gb[0], saB[0], hB[0], z2, Hs, b1p, smu, s_sh, l_sh, r_sh, h_sh);
        passA_blk<4>(Gb[1], saB[1], hB[1], z2, Hs, b1p, smu, s_sh, l_sh, r_sh, h_sh);
        passA_blk<6>(Gb[2], saB[2], hB[2], z2, Hs, b1p, smu, s_sh, l_sh, r_sh, h_sh);
        passA_blk<8>(Gb[3], saB[3], hB[3], z2, Hs, b1p, smu, s_sh, l_sh, r_sh, h_sh);

        // ---- quad combine (2-stage butterfly sum) + add Q ----
        #pragma unroll
        for (int e = 0; e < 55; e++){
            float v = Hs[e];
            v += __shfl_xor_sync(0xffffffffu, v, 1);
            v += __shfl_xor_sync(0xffffffffu, v, 2);
            Hs[e] = v;
        }
        #pragma unroll
        for (int a = 0; a < NU; a++)
            #pragma unroll
            for (int b = 0; b <= a; b++)
                Hs[(a*(a+1))/2+b] += Q_sh[a*NU+b];
        #pragma unroll
        for (int j = 0; j < 5; j++){
            b1p[j] = add2(b1p[j], sh64(b1p[j], 1));
            b1p[j] = add2(b1p[j], sh64(b1p[j], 2));
        }
        float b1[NU];
        #pragma unroll
        for (int j = 0; j < 5; j++) upk(b1p[j], b1[2*j], b1[2*j+1]);

        // ---- identity rows (uniform in all 4 threads, post-combine) ----
        #pragma unroll
        for (int m = 0; m < NU; m++){
            float zlo, zhi; upk(z2[m>>1], zlo, zhi);
            float zm = (m & 1) ? zhi : zlo;
            float sm = s_id[m], lm = l_id[m];
            float ivs = frcp(sm);
            float rp = zm + sm - h_sh[m];
            b1[m] += fmaf(lm, rp, smu)*ivs;
            Hs[(m*(m+1))/2+m] += lm*ivs;
        }

        // ---- rhs (in place -> becomes dz) ----
        float dz[NU];
        #pragma unroll
        for (int i = 0; i < NU; i++){
            u64 acc = pk(0.f, 0.f);
            #pragma unroll
            for (int j = 0; j < 5; j++){
                float2 qv = *(const float2*)&Q_sh[i*NU + 2*j];
                acc = fma2(pk(qv.x, qv.y), z2[j], acc);
            }
            float qx, qy; upk(acc, qx, qy);
            dz[i] = -(p[i] + b1[i] + qx + qy);
        }
        // ---- Cholesky (duplicated, uniform) ----
        #pragma unroll
        for (int k = 0; k < NU; k++){
            float inv = rsqrtf(Hs[(k*(k+1))/2+k]);
            Hs[(k*(k+1))/2+k] = inv;
            #pragma unroll
            for (int i = k+1; i < NU; i++) Hs[(i*(i+1))/2+k] *= inv;
            #pragma unroll
            for (int j = k+1; j < NU; j++){
                float ljk = Hs[(j*(j+1))/2+k];
                #pragma unroll
                for (int i = j; i < NU; i++)
                    Hs[(i*(i+1))/2+j] = fmaf(-Hs[(i*(i+1))/2+k], ljk, Hs[(i*(i+1))/2+j]);
            }
        }
        #pragma unroll
        for (int i = 0; i < NU; i++){
            float tt = dz[i];
            #pragma unroll
            for (int j = 0; j < i; j++) tt = fmaf(-Hs[(i*(i+1))/2+j], dz[j], tt);
            dz[i] = tt * Hs[(i*(i+1))/2+i];
        }
        #pragma unroll
        for (int i = NU-1; i >= 0; i--){
            float tt = dz[i];
            #pragma unroll
            for (int j = i+1; j < NU; j++) tt = fmaf(-Hs[(j*(j+1))/2+i], dz[j], tt);
            dz[i] = tt * Hs[(i*(i+1))/2+i];
        }
        u64 dz2[5];
        #pragma unroll
        for (int j = 0; j < 5; j++) dz2[j] = pk(dz[2*j], dz[2*j+1]);

        // ---- pass B1: step-length ratios ----
        float qm = 0.f;
        #pragma unroll
        for (int m = 0; m < NU; m++){           // identity rows, uniform
            float zlo, zhi; upk(z2[m>>1], zlo, zhi);
            float zm = (m & 1) ? zhi : zlo;
            float sm = s_id[m], lm = l_id[m];
            float rp = zm + sm - h_sh[m];
            float ds = -(rp + dz[m]);
            float rc = fmaf(sm, lm, -smu);
            float ivs = frcp(sm), ivl = frcp(lm);
            float dlam = -fmaf(lm, ds, rc)*ivs;
            qm = fmaxf(qm, fmaxf(-ds*ivs, -dlam*ivl));
        }
        passB1_blk<2>(Gb[0], saB[0], dz2, smu, qm, s_sh, l_sh, r_sh);
        passB1_blk<4>(Gb[1], saB[1], dz2, smu, qm, s_sh, l_sh, r_sh);
        passB1_blk<6>(Gb[2], saB[2], dz2, smu, qm, s_sh, l_sh, r_sh);
        passB1_blk<8>(Gb[3], saB[3], dz2, smu, qm, s_sh, l_sh, r_sh);
        qm = fmaxf(qm, __shfl_xor_sync(0xffffffffu, qm, 1));
        qm = fmaxf(qm, __shfl_xor_sync(0xffffffffu, qm, 2));
        float alpha = fminf(1.f, 0.99f*frcp(qm));

        // ---- pass B2: update s, lam; accumulate next-iter musum ----
        float msn = 0.f;
        #pragma unroll
        for (int bi = 0; bi < 4; bi++){
            #pragma unroll
            for (int j = 0; j < 8; j++){
                const int sa = saB[bi] + j;
                float sm = s_sh[sa], lm = l_sh[sa];
                float ds = r_sh[sa];
                float rc = fmaf(sm, lm, -smu);
                float ivs = frcp(sm);
                float dlam = -fmaf(lm, ds, rc)*ivs;
                float sn = fmaf(alpha, ds, sm);
                float ln = fmaf(alpha, dlam, lm);
                s_sh[sa] = sn; l_sh[sa] = ln;
                msn = fmaf(sn, ln, msn);
            }
        }
        msn += __shfl_xor_sync(0xffffffffu, msn, 1);
        msn += __shfl_xor_sync(0xffffffffu, msn, 2);
        #pragma unroll
        for (int m = 0; m < NU; m++){           // identity rows, uniform, post-combine
            float zlo, zhi; upk(z2[m>>1], zlo, zhi);
            float zm = (m & 1) ? zhi : zlo;
            float sm = s_id[m], lm = l_id[m];
            float rp = zm + sm - h_sh[m];
            float ds = -(rp + dz[m]);
            float rc = fmaf(sm, lm, -smu);
            float ivs = frcp(sm);
            float dlam = -fmaf(lm, ds, rc)*ivs;
            float sn = fmaf(alpha, ds, sm);
            float ln = fmaf(alpha, dlam, lm);
            s_id[m] = sn; l_id[m] = ln;
            msn = fmaf(sn, ln, msn);
        }
        musum = msn;

        u64 al2 = pk(alpha, alpha);
        #pragma unroll
        for (int j = 0; j < 5; j++) z2[j] = fma2(al2, dz2[j], z2[j]);
    }
    if (r == 0){
        float z0, z1; upk(z2[0], z0, z1);
        out[item] = z0;
    }
}

// ---------------- launch ----------------
extern "C" void kernel_launch(void* const* d_in, const int* in_sizes, int n_in,
                              void* d_out, int out_size)
{
    (void)in_sizes; (void)n_in; (void)out_size;
    const float* x    = (const float*)d_in[0];
    const float* w1   = (const float*)d_in[1];
    const float* b1   = (const float*)d_in[2];
    const float* w2   = (const float*)d_in[3];
    const float* b2   = (const float*)d_in[4];
    const float* bn1g = (const float*)d_in[5];
    const float* bn1b = (const float*)d_in[6];
    const float* bn2g = (const float*)d_in[7];
    const float* bn2b = (const float*)d_in[8];
    const float* L    = (const float*)d_in[9];
    const float* LP   = (const float*)d_in[10];
    const float* LR   = (const float*)d_in[11];
    const float* A    = (const float*)d_in[12];
    const float* Bm   = (const float*)d_in[13];
    const float* u0   = (const float*)d_in[14];
    const float* s0   = (const float*)d_in[15];
    float* out = (float*)d_out;

    const int ipm_smem = 3*IPB*SROW*(int)sizeof(float);   // 49,536 B
    cudaFuncSetAttribute(ipm_kernel, cudaFuncAttributeMaxDynamicSharedMemorySize, ipm_smem);

    build_qp<<<1, 256>>>(L, LP, LR, A, Bm, u0, s0);
    fc1_kernel<<<FC1_BLOCKS, 256>>>(x, w1, b1);
    fold_all<<<NU, 256>>>(w2, b2, bn1g, bn1b);
    fc2_kernel<<<FC2_BLOCKS, 256>>>();
    bn2_fin<<<1, 256>>>(bn2g, bn2b);
    ipm_kernel<<<NB/IPB, 128, ipm_smem>>>(out);
}

// round 6
// speedup vs baseline: 2.6135x; 2.6135x over previous
#include <cuda_runtime.h>

#define NB   16384
#define NH   1024
#define NIN  32
#define NU   10
#define MI   138
#define ITER 30
#define SIGMA 0.1f
#define FC1_BLOCKS (NB/128)   // 128
#define FC2_BLOCKS (NB/16)    // 1024

#define IPB  64               // items per IPM block (128 threads, 2 per item)
#define SROW 129              // odd stride -> conflict-free pair access

typedef unsigned long long u64;

// ---------------- device scratch (static, no allocs) ----------------
__device__ float g_h1[NB*NH];              // 64 MB
__device__ float g_bn1p[FC1_BLOCKS*NH];
__device__ float g_bn1q[FC1_BLOCKS*NH];
__device__ float g_W2f[NU*NH];
__device__ float g_b2f[NU];
__device__ float g_t2[NB*NU];
__device__ float g_bn2p[FC2_BLOCKS*NU];
__device__ float g_bn2q[FC2_BLOCKS*NU];
__device__ float g_bn2ac[2*NU];
__device__ float g_Qhat[NU*NU];
__device__ float g_G[MI*NU];
__device__ float g_h[MI];

__device__ __forceinline__ float frcp(float x){ float r; asm("rcp.approx.f32 %0, %1;" : "=f"(r) : "f"(x)); return r; }
__device__ __forceinline__ float lrelu(float v){ return v > 0.f ? v : 0.2f*v; }

// ---- packed f32x2 helpers ----
__device__ __forceinline__ u64 pk(float x, float y){
    u64 r; asm("mov.b64 %0, {%1,%2};" : "=l"(r) : "f"(x), "f"(y)); return r;
}
__device__ __forceinline__ void upk(u64 v, float& x, float& y){
    asm("mov.b64 {%0,%1}, %2;" : "=f"(x), "=f"(y) : "l"(v));
}
__device__ __forceinline__ u64 fma2(u64 a, u64 b, u64 c){
    u64 d; asm("fma.rn.f32x2 %0, %1, %2, %3;" : "=l"(d) : "l"(a), "l"(b), "l"(c)); return d;
}
__device__ __forceinline__ u64 mul2(u64 a, u64 b){
    u64 d; asm("mul.rn.f32x2 %0, %1, %2;" : "=l"(d) : "l"(a), "l"(b)); return d;
}
__device__ __forceinline__ u64 add2(u64 a, u64 b){
    u64 d; asm("add.rn.f32x2 %0, %1, %2;" : "=l"(d) : "l"(a), "l"(b)); return d;
}
__device__ __forceinline__ u64 sh64(u64 v){
    return __shfl_xor_sync(0xffffffffu, v, 1);
}

// ---------------- K0: build QP (Q_hat, G, h) -- one block ----------------
__global__ void build_qp(const float* __restrict__ L, const float* __restrict__ LP,
                         const float* __restrict__ LR, const float* __restrict__ A,
                         const float* __restrict__ Bm, const float* __restrict__ u0,
                         const float* __restrict__ s0)
{
    __shared__ float Q[32*32], P[32*32], R[4], pw[4][64], Bh[128*NU], Ms[128*NU];
    const int t = threadIdx.x; // 256 threads

    for (int e = t; e < 1024; e += 256){
        int i = e >> 5, j = e & 31;
        int kmax = i < j ? i : j;
        float aq = (i==j) ? 1e-4f : 0.f;
        float ap = aq;
        for (int k = 0; k <= kmax; k++){
            aq = fmaf(L [i*32+k], L [j*32+k], aq);
            ap = fmaf(LP[i*32+k], LP[j*32+k], ap);
        }
        Q[e] = aq; P[e] = ap;
    }
    if (t < 4){
        int i = t >> 1, j = t & 1;
        int kmax = i < j ? i : j;
        float a = (i==j) ? 1e-4f : 0.f;
        for (int k = 0; k <= kmax; k++) a = fmaf(LR[i*2+k], LR[j*2+k], a);
        R[t] = a;
    }
    if (t < 64) pw[0][t] = Bm[t];
    __syncthreads();
    for (int s = 1; s < 4; s++){
        if (t < 64){
            int r = t >> 1, c = t & 1;
            float acc = 0.f;
            for (int k = 0; k < 32; k++) acc = fmaf(A[r*32+k], pw[s-1][k*2+c], acc);
            pw[s][t] = acc;
        }
        __syncthreads();
    }
    for (int e = t; e < 128*NU; e += 256){
        int row = e / NU, col = e - row*NU;
        int bi = row >> 5, r = row & 31, bj = col >> 1, c = col & 1;
        Bh[e] = (bj <= bi) ? pw[bi-bj][r*2+c] : 0.f;
    }
    __syncthreads();
    for (int e = t; e < 128*NU; e += 256){
        int row = e / NU, col = e - row*NU;
        int b = row >> 5, r = row & 31;
        const float* Qb = (b < 3) ? Q : P;
        float acc = 0.f;
        for (int k = 0; k < 32; k++) acc = fmaf(Qb[r*32+k], Bh[(b*32+k)*NU+col], acc);
        Ms[e] = acc;
    }
    __syncthreads();
    if (t < 100){
        int a = t / NU, b = t - (t/NU)*NU;
        float acc = ((a>>1) == (b>>1)) ? R[(a&1)*2+(b&1)] : 0.f;
        for (int row = 0; row < 128; row++) acc = fmaf(Bh[row*NU+a], Ms[row*NU+b], acc);
        g_Qhat[t] = acc;
    }
    for (int e = t; e < MI*NU; e += 256){
        int row = e / NU, col = e - (e/NU)*NU;
        g_G[e] = (row < NU) ? ((row==col) ? 1.f : 0.f) : Bh[(row-NU)*NU+col];
    }
    if (t < MI){
        float acc = s0[t];
        if (t < NU) acc += u0[t];
        else { for (int j = 0; j < NU; j++) acc = fmaf(Bh[(t-NU)*NU+j], u0[j], acc); }
        g_h[t] = acc;
    }
}

// ---------------- K1: fc1 + leaky_relu + bn1 partial stats ----------------
__global__ void __launch_bounds__(256) fc1_kernel(const float* __restrict__ x,
    const float* __restrict__ W1, const float* __restrict__ b1)
{
    __shared__ __align__(16) float xs[128*32];
    const int t = threadIdx.x;
    const int row0 = blockIdx.x * 128;
    {
        const float4* src = (const float4*)(x + row0*32);
        float4* dst = (float4*)xs;
        for (int e = t; e < 1024; e += 256) dst[e] = src[e];
    }
    __syncthreads();
    #pragma unroll
    for (int ff = 0; ff < 4; ff++){
        const int f = t + ff*256;
        float w[32];
        const float4* wp = (const float4*)(W1 + f*32);
        #pragma unroll
        for (int k = 0; k < 8; k++){
            float4 v = wp[k];
            w[4*k+0]=v.x; w[4*k+1]=v.y; w[4*k+2]=v.z; w[4*k+3]=v.w;
        }
        const float bias = b1[f];
        float sum = 0.f, sq = 0.f;
        for (int r = 0; r < 128; r++){
            float acc = bias;
            const float4* xp = (const float4*)(xs + r*32);
            #pragma unroll
            for (int k = 0; k < 8; k++){
                float4 xv = xp[k];
                acc = fmaf(xv.x, w[4*k+0], acc);
                acc = fmaf(xv.y, w[4*k+1], acc);
                acc = fmaf(xv.z, w[4*k+2], acc);
                acc = fmaf(xv.w, w[4*k+3], acc);
            }
            float v = lrelu(acc);
            g_h1[(row0+r)*NH + f] = v;
            sum += v; sq = fmaf(v, v, sq);
        }
        g_bn1p[blockIdx.x*NH + f] = sum;
        g_bn1q[blockIdx.x*NH + f] = sq;
    }
}

// ---------------- K2: bn1 finalize fused with fc2-weight fold ----------------
__global__ void fold_all(const float* __restrict__ W2, const float* __restrict__ b2,
                         const float* __restrict__ g1, const float* __restrict__ beta1)
{
    __shared__ float red[256];
    const int u = blockIdx.x, t = threadIdx.x;
    float dot = 0.f;
    for (int k = t; k < NH; k += 256){
        float sum = 0.f, sq = 0.f;
        for (int b = 0; b < FC1_BLOCKS; b++){
            sum += g_bn1p[b*NH + k];
            sq  += g_bn1q[b*NH + k];
        }
        float mu  = sum * (1.f/(float)NB);
        float var = sq  * (1.f/(float)NB) - mu*mu;
        float a = g1[k]*rsqrtf(var + 1e-5f);
        float c = beta1[k] - mu*a;
        float wv = W2[u*NH + k];
        g_W2f[u*NH + k] = wv * a;
        dot = fmaf(wv, c, dot);
    }
    red[t] = dot; __syncthreads();
    for (int s = 128; s > 0; s >>= 1){
        if (t < s) red[t] += red[t+s];
        __syncthreads();
    }
    if (t == 0) g_b2f[u] = b2[u] + red[0];
}

// ---------------- K3: fc2 (2 items per warp) + leaky_relu + bn2 stats ----------------
__global__ void __launch_bounds__(256) fc2_kernel()
{
    __shared__ float Ws[NU*NH];
    __shared__ float bs[NU];
    __shared__ float wt2[16][NU];
    const int t = threadIdx.x, lane = t & 31, wid = t >> 5;
    for (int e = t; e < NU*NH; e += 256) Ws[e] = g_W2f[e];
    if (t < NU) bs[t] = g_b2f[t];
    __syncthreads();
    const int item0 = blockIdx.x*16 + wid*2;
    float acc0[NU], acc1[NU];
    #pragma unroll
    for (int u = 0; u < NU; u++){ acc0[u] = 0.f; acc1[u] = 0.f; }
    const float* hrow0 = g_h1 + item0*NH;
    const float* hrow1 = hrow0 + NH;
    for (int j = 0; j < 32; j++){
        float hv0 = hrow0[j*32 + lane];
        float hv1 = hrow1[j*32 + lane];
        #pragma unroll
        for (int u = 0; u < NU; u++){
            float wv = Ws[u*NH + j*32 + lane];
            acc0[u] = fmaf(hv0, wv, acc0[u]);
            acc1[u] = fmaf(hv1, wv, acc1[u]);
        }
    }
    #pragma unroll
    for (int u = 0; u < NU; u++){
        #pragma unroll
        for (int off = 16; off > 0; off >>= 1){
            acc0[u] += __shfl_xor_sync(0xffffffffu, acc0[u], off);
            acc1[u] += __shfl_xor_sync(0xffffffffu, acc1[u], off);
        }
    }
    if (lane == 0){
        #pragma unroll
        for (int u = 0; u < NU; u++){
            float v0 = lrelu(acc0[u] + bs[u]);
            float v1 = lrelu(acc1[u] + bs[u]);
            g_t2[item0*NU + u] = v0;
            g_t2[(item0+1)*NU + u] = v1;
            wt2[wid*2][u] = v0;
            wt2[wid*2+1][u] = v1;
        }
    }
    __syncthreads();
    if (t < NU){
        float s = 0.f, q = 0.f;
        #pragma unroll
        for (int w = 0; w < 16; w++){ float v = wt2[w][t]; s += v; q = fmaf(v, v, q); }
        g_bn2p[blockIdx.x*NU + t] = s;
        g_bn2q[blockIdx.x*NU + t] = q;
    }
}

// ---------------- K4: finalize bn2 ----------------
__global__ void bn2_fin(const float* __restrict__ g2, const float* __restrict__ beta2)
{
    __shared__ float red[256*20];
    const int t = threadIdx.x;
    float loc[20];
    #pragma unroll
    for (int j = 0; j < 20; j++) loc[j] = 0.f;
    for (int b = t; b < FC2_BLOCKS; b += 256){
        #pragma unroll
        for (int u = 0; u < NU; u++){
            loc[u]    += g_bn2p[b*NU + u];
            loc[10+u] += g_bn2q[b*NU + u];
        }
    }
    #pragma unroll
    for (int j = 0; j < 20; j++) red[t*20 + j] = loc[j];
    __syncthreads();
    for (int s = 128; s > 0; s >>= 1){
        if (t < s){
            #pragma unroll
            for (int j = 0; j < 20; j++) red[t*20 + j] += red[(t+s)*20 + j];
        }
        __syncthreads();
    }
    if (t < NU){
        float mu  = red[t]    * (1.f/(float)NB);
        float var = red[10+t] * (1.f/(float)NB) - mu*mu;
        float a = g2[t]*rsqrtf(var + 1e-5f);
        g_bn2ac[t]      = a;
        g_bn2ac[NU + t] = beta2[t] - mu*a;
    }
}

// ---------------- K5: batched IPM, one item per THREAD PAIR ----------------
#define HOFF0 0
#define HOFF1 1
#define HOFF2 2
#define HOFF3 4
#define HOFF4 6
#define HOFF5 9
#define HOFF6 12
#define HOFF7 16
#define HOFF8 20
#define HOFF9 25

template<int K>
__device__ __forceinline__ void passA_blk(const float* __restrict__ Gblk, int sa0, int hBase,
    const u64* z2, u64* H2, u64* b1p, float smu,
    const float* s_sh, const float* l_sh, const float* h_sh)
{
    const int HOFF[10] = {HOFF0,HOFF1,HOFF2,HOFF3,HOFF4,HOFF5,HOFF6,HOFF7,HOFF8,HOFF9};
    const int KH = K/2;
    #pragma unroll 4
    for (int j = 0; j < 16; j++){
        const int sa = sa0 + j;
        float sm = s_sh[sa], lm = l_sh[sa];
        float ivs = frcp(sm);
        float w = lm*ivs;
        float2 gv[KH]; u64 g2[KH];
        #pragma unroll
        for (int jj = 0; jj < KH; jj++){
            gv[jj] = *(const float2*)&Gblk[j*K + 2*jj];
            g2[jj] = pk(gv[jj].x, gv[jj].y);
        }
        u64 acc = pk(0.f, 0.f);
        #pragma unroll
        for (int jj = 0; jj < KH; jj++) acc = fma2(g2[jj], z2[jj], acc);
        float gx, gy; upk(acc, gx, gy);
        float rp = (gx + gy) + sm - h_sh[hBase + j];
        float coef = fmaf(lm, rp, smu)*ivs;
        u64 w2v = pk(w, w), c2 = pk(coef, coef);
        u64 wgp[KH];
        #pragma unroll
        for (int jj = 0; jj < KH; jj++){
            wgp[jj] = mul2(w2v, g2[jj]);
            b1p[jj] = fma2(c2, g2[jj], b1p[jj]);
        }
        #pragma unroll
        for (int a = 0; a < K; a++){
            float ga = (a & 1) ? gv[a>>1].y : gv[a>>1].x;
            u64 ga2 = pk(ga, ga);
            #pragma unroll
            for (int pi = 0; pi <= (a>>1); pi++)
                H2[HOFF[a]+pi] = fma2(ga2, wgp[pi], H2[HOFF[a]+pi]);
        }
    }
}

template<int K>
__device__ __forceinline__ void passB1_blk(const float* __restrict__ Gblk, int sa0, int hBase,
    const u64* zpd2, float smu, float& q,
    const float* s_sh, const float* l_sh, float* r_sh, const float* h_sh)
{
    const int KH = K/2;
    #pragma unroll 4
    for (int j = 0; j < 16; j++){
        const int sa = sa0 + j;
        float sm = s_sh[sa], lm = l_sh[sa];
        u64 acc = pk(0.f, 0.f);
        #pragma unroll
        for (int jj = 0; jj < KH; jj++){
            float2 gvj = *(const float2*)&Gblk[j*K + 2*jj];
            acc = fma2(pk(gvj.x, gvj.y), zpd2[jj], acc);
        }
        float gx, gy; upk(acc, gx, gy);
        float ds = -((gx + gy) + sm - h_sh[hBase + j]);
        float rc = fmaf(sm, lm, -smu);
        float ivs = frcp(sm), ivl = frcp(lm);
        float dlam = -fmaf(lm, ds, rc)*ivs;
        q = fmaxf(q, fmaxf(-ds*ivs, -dlam*ivl));
        r_sh[sa] = ds;
    }
}

__global__ void __launch_bounds__(128, 2) ipm_kernel(float* __restrict__ out)
{
    extern __shared__ float dyn[];
    float* s_sh = dyn;                    // IPB*SROW
    float* l_sh = dyn +   IPB*SROW;
    float* r_sh = dyn + 2*IPB*SROW;
    __shared__ __align__(8) float G_sh[704];
    __shared__ float h_sh[MI];
    __shared__ __align__(8) float Q_sh[NU*NU];
    __shared__ float ac_sh[2*NU];
    const int HOFF[10] = {HOFF0,HOFF1,HOFF2,HOFF3,HOFF4,HOFF5,HOFF6,HOFF7,HOFF8,HOFF9};
    const int GA[4] = {0, 80, 224, 432};
    const int GB[4] = {48, 160, 336, 576};

    const int tid = threadIdx.x;
    const int r = tid & 1, q = tid >> 1;
    const int item = blockIdx.x*IPB + q;

    // G packed: K-block bi holds rows (local j=0..31) with K=2bi+2 nonzero cols;
    // halves (j<16 / j>=16) placed 16 words apart mod 32 -> conflict-free dual broadcast
    {
        int mm = tid;  // 0..127, one structured row per thread
        int bi = mm >> 5, lr = mm & 31, hf = lr >> 4, j = lr & 15, K = 2*bi + 2;
        int base = (hf ? GB[bi] : GA[bi]) + j*K;
        for (int c = 0; c < K; c++) G_sh[base + c] = g_G[(10+mm)*NU + c];
    }
    for (int i = tid; i < MI; i += 128) h_sh[i] = g_h[i];
    if (tid < 100) Q_sh[tid] = g_Qhat[tid];
    if (tid < 20)  ac_sh[tid] = g_bn2ac[tid];
    __syncthreads();

    float z[NU], p[NU];
    u64 z2[5];
    #pragma unroll
    for (int u = 0; u < NU; u++){
        p[u] = fmaf(g_t2[item*NU+u], ac_sh[u], ac_sh[NU+u]);
        z[u] = 0.f;
    }
    #pragma unroll
    for (int j = 0; j < 5; j++) z2[j] = pk(0.f, 0.f);

    float s_id[5], l_id[5], ds_id[5];
    #pragma unroll
    for (int j = 0; j < 5; j++){ s_id[j] = 1.f; l_id[j] = 1.f; }

    // this thread's smem rows: per K-block bi, rows mm = 32*bi + 16*r + j
    int saB[4], hB[4];
    const float* Gb[4];
    #pragma unroll
    for (int bi = 0; bi < 4; bi++){
        int mm0 = 32*bi + 16*r;
        saB[bi] = q*SROW + mm0;
        hB[bi]  = 10 + mm0;
        Gb[bi]  = &G_sh[r ? GB[bi] : GA[bi]];
        #pragma unroll 4
        for (int j = 0; j < 16; j++){
            s_sh[saB[bi]+j] = 1.f; l_sh[saB[bi]+j] = 1.f;
        }
    }
    float musum = (float)MI;   // s=lam=1 initially

    for (int it = 0; it < ITER; it++){
        float smu = musum * (SIGMA/(float)MI);
        // ---- pass A: partial H2/b1p over this thread's 64 rows ----
        u64 H2[30], b1p[5];
        #pragma unroll
        for (int e = 0; e < 30; e++) H2[e] = pk(0.f, 0.f);
        #pragma unroll
        for (int j = 0; j < 5; j++) b1p[j] = pk(0.f, 0.f);

        // identity rows (registers), split 0..4 / 5..9 by parity, pre-combine
        #pragma unroll
        for (int j = 0; j < 5; j++){
            const int m = r ? (5 + j) : j;
            float sm = s_id[j], lm = l_id[j];
            float ivs = frcp(sm);
            float w = lm*ivs;
            float rp = z[m] + sm - h_sh[m];
            float c = fmaf(lm, rp, smu)*ivs;
            b1p[m>>1] = add2(b1p[m>>1], (m&1) ? pk(0.f,c) : pk(c,0.f));
            H2[HOFF[m]+(m>>1)] = add2(H2[HOFF[m]+(m>>1)], (m&1) ? pk(0.f,w) : pk(w,0.f));
        }

        passA_blk<2>(Gb[0], saB[0], hB[0], z2, H2, b1p, smu, s_sh, l_sh, h_sh);
        passA_blk<4>(Gb[1], saB[1], hB[1], z2, H2, b1p, smu, s_sh, l_sh, h_sh);
        passA_blk<6>(Gb[2], saB[2], hB[2], z2, H2, b1p, smu, s_sh, l_sh, h_sh);
        passA_blk<8>(Gb[3], saB[3], hB[3], z2, H2, b1p, smu, s_sh, l_sh, h_sh);

        // ---- pair combine ----
        #pragma unroll
        for (int e = 0; e < 30; e++) H2[e] = add2(H2[e], sh64(H2[e]));
        #pragma unroll
        for (int j = 0; j < 5; j++) b1p[j] = add2(b1p[j], sh64(b1p[j]));

        // ---- unpack + add Q ----
        float Hs[55];
        #pragma unroll
        for (int a = 0; a < NU; a++){
            #pragma unroll
            for (int pi = 0; pi <= (a>>1); pi++){
                float x, y; upk(H2[HOFF[a]+pi], x, y);
                Hs[(a*(a+1))/2 + 2*pi] = x + Q_sh[a*NU + 2*pi];
                if (2*pi+1 <= a) Hs[(a*(a+1))/2 + 2*pi+1] = y + Q_sh[a*NU + 2*pi+1];
            }
        }
        float b1[NU];
        #pragma unroll
        for (int j = 0; j < 5; j++) upk(b1p[j], b1[2*j], b1[2*j+1]);

        // ---- rhs (in place -> dz) ----
        float dz[NU];
        #pragma unroll
        for (int i = 0; i < NU; i++){
            u64 acc = pk(0.f, 0.f);
            #pragma unroll
            for (int j = 0; j < 5; j++){
                float2 qv = *(const float2*)&Q_sh[i*NU + 2*j];
                acc = fma2(pk(qv.x, qv.y), z2[j], acc);
            }
            float qx, qy; upk(acc, qx, qy);
            dz[i] = -(p[i] + b1[i] + qx + qy);
        }
        // ---- Cholesky (duplicated in both threads) ----
        #pragma unroll
        for (int k = 0; k < NU; k++){
            float inv = rsqrtf(Hs[(k*(k+1))/2+k]);
            Hs[(k*(k+1))/2+k] = inv;
            #pragma unroll
            for (int i = k+1; i < NU; i++) Hs[(i*(i+1))/2+k] *= inv;
            #pragma unroll
            for (int j = k+1; j < NU; j++){
                float ljk = Hs[(j*(j+1))/2+k];
                #pragma unroll
                for (int i = j; i < NU; i++)
                    Hs[(i*(i+1))/2+j] = fmaf(-Hs[(i*(i+1))/2+k], ljk, Hs[(i*(i+1))/2+j]);
            }
        }
        #pragma unroll
        for (int i = 0; i < NU; i++){
            float tt = dz[i];
            #pragma unroll
            for (int j = 0; j < i; j++) tt = fmaf(-Hs[(i*(i+1))/2+j], dz[j], tt);
            dz[i] = tt * Hs[(i*(i+1))/2+i];
        }
        #pragma unroll
        for (int i = NU-1; i >= 0; i--){
            float tt = dz[i];
            #pragma unroll
            for (int j = i+1; j < NU; j++) tt = fmaf(-Hs[(j*(j+1))/2+i], dz[j], tt);
            dz[i] = tt * Hs[(i*(i+1))/2+i];
        }
        u64 dz2[5], zpd2[5];
        #pragma unroll
        for (int j = 0; j < 5; j++){
            dz2[j] = pk(dz[2*j], dz[2*j+1]);
            zpd2[j] = add2(z2[j], dz2[j]);
        }

        // ---- pass B1: step-length ratios (ds from G·(z+dz)) ----
        float qm = 0.f;
        #pragma unroll
        for (int j = 0; j < 5; j++){             // identity rows
            const int m = r ? (5 + j) : j;
            float sm = s_id[j], lm = l_id[j];
            float ds = -((z[m] + dz[m]) + sm - h_sh[m]);
            float rc = fmaf(sm, lm, -smu);
            float ivs = frcp(sm), ivl = frcp(lm);
            float dlam = -fmaf(lm, ds, rc)*ivs;
            qm = fmaxf(qm, fmaxf(-ds*ivs, -dlam*ivl));
            ds_id[j] = ds;
        }
        passB1_blk<2>(Gb[0], saB[0], hB[0], zpd2, smu, qm, s_sh, l_sh, r_sh, h_sh);
        passB1_blk<4>(Gb[1], saB[1], hB[1], zpd2, smu, qm, s_sh, l_sh, r_sh, h_sh);
        passB1_blk<6>(Gb[2], saB[2], hB[2], zpd2, smu, qm, s_sh, l_sh, r_sh, h_sh);
        passB1_blk<8>(Gb[3], saB[3], hB[3], zpd2, smu, qm, s_sh, l_sh, r_sh, h_sh);
        qm = fmaxf(qm, __shfl_xor_sync(0xffffffffu, qm, 1));
        float alpha = fminf(1.f, 0.99f*frcp(qm));

        // ---- pass B2: update s, lam; accumulate next-iter musum ----
        float msn = 0.f;
        #pragma unroll
        for (int j = 0; j < 5; j++){             // identity rows
            float sm = s_id[j], lm = l_id[j];
            float ds = ds_id[j];
            float rc = fmaf(sm, lm, -smu);
            float ivs = frcp(sm);
            float dlam = -fmaf(lm, ds, rc)*ivs;
            float sn = fmaf(alpha, ds, sm);
            float ln = fmaf(alpha, dlam, lm);
            s_id[j] = sn; l_id[j] = ln;
            msn = fmaf(sn, ln, msn);
        }
        #pragma unroll
        for (int bi = 0; bi < 4; bi++){
            #pragma unroll 4
            for (int j = 0; j < 16; j++){
                const int sa = saB[bi] + j;
                float sm = s_sh[sa], lm = l_sh[sa];
                float ds = r_sh[sa];
                float rc = fmaf(sm, lm, -smu);
                float ivs = frcp(sm);
                float dlam = -fmaf(lm, ds, rc)*ivs;
                float sn = fmaf(alpha, ds, sm);
                float ln = fmaf(alpha, dlam, lm);
                s_sh[sa] = sn; l_sh[sa] = ln;
                msn = fmaf(sn, ln, msn);
            }
        }
        msn += __shfl_xor_sync(0xffffffffu, msn, 1);
        musum = msn;

        #pragma unroll
        for (int u = 0; u < NU; u++) z[u] = fmaf(alpha, dz[u], z[u]);
        #pragma unroll
        for (int j = 0; j < 5; j++) z2[j] = pk(z[2*j], z[2*j+1]);
    }
    if (r == 0) out[item] = z[0];
}

// ---------------- launch ----------------
extern "C" void kernel_launch(void* const* d_in, const int* in_sizes, int n_in,
                              void* d_out, int out_size)
{
    (void)in_sizes; (void)n_in; (void)out_size;
    const float* x    = (const float*)d_in[0];
    const float* w1   = (const float*)d_in[1];
    const float* b1   = (const float*)d_in[2];
    const float* w2   = (const float*)d_in[3];
    const float* b2   = (const float*)d_in[4];
    const float* bn1g = (const float*)d_in[5];
    const float* bn1b = (const float*)d_in[6];
    const float* bn2g = (const float*)d_in[7];
    const float* bn2b = (const float*)d_in[8];
    const float* L    = (const float*)d_in[9];
    const float* LP   = (const float*)d_in[10];
    const float* LR   = (const float*)d_in[11];
    const float* A    = (const float*)d_in[12];
    const float* Bm   = (const float*)d_in[13];
    const float* u0   = (const float*)d_in[14];
    const float* s0   = (const float*)d_in[15];
    float* out = (float*)d_out;

    const int ipm_smem = 3*IPB*SROW*(int)sizeof(float);   // 99,072 B -> 2 blocks/SM
    cudaFuncSetAttribute(ipm_kernel, cudaFuncAttributeMaxDynamicSharedMemorySize, ipm_smem);

    build_qp<<<1, 256>>>(L, LP, LR, A, Bm, u0, s0);
    fc1_kernel<<<FC1_BLOCKS, 256>>>(x, w1, b1);
    fold_all<<<NU, 256>>>(w2, b2, bn1g, bn1b);
    fc2_kernel<<<FC2_BLOCKS, 256>>>();
    bn2_fin<<<1, 256>>>(bn2g, bn2b);
    ipm_kernel<<<NB/IPB, 128, ipm_smem>>>(out);
}

// round 7
// speedup vs baseline: 3.2408x; 1.2400x over previous
#include <cuda_runtime.h>

#define NB   16384
#define NH   1024
#define NIN  32
#define NU   10
#define MI   138
#define ITER 30
#define SIGMA 0.1f
#define FC1_BLOCKS (NB/128)   // 128
#define FC2_BLOCKS (NB/16)    // 1024

#define IPB  64               // items per IPM block (128 threads, 2 per item)
#define SROW 129              // odd stride -> conflict-free pair access

typedef unsigned long long u64;

// ---------------- device scratch (static, no allocs) ----------------
__device__ float g_h1[NB*NH];              // 64 MB
__device__ float g_bn1p[FC1_BLOCKS*NH];
__device__ float g_bn1q[FC1_BLOCKS*NH];
__device__ float g_W2f[NU*NH];
__device__ float g_b2f[NU];
__device__ float g_t2[NB*NU];
__device__ float g_bn2p[FC2_BLOCKS*NU];
__device__ float g_bn2q[FC2_BLOCKS*NU];
__device__ float g_bn2ac[2*NU];
__device__ float g_Qhat[NU*NU];
__device__ float g_G[MI*NU];
__device__ float g_h[MI];

__device__ __forceinline__ float frcp(float x){ float r; asm("rcp.approx.f32 %0, %1;" : "=f"(r) : "f"(x)); return r; }
__device__ __forceinline__ float lrelu(float v){ return v > 0.f ? v : 0.2f*v; }

// ---- packed f32x2 helpers ----
__device__ __forceinline__ u64 pk(float x, float y){
    u64 r; asm("mov.b64 %0, {%1,%2};" : "=l"(r) : "f"(x), "f"(y)); return r;
}
__device__ __forceinline__ void upk(u64 v, float& x, float& y){
    asm("mov.b64 {%0,%1}, %2;" : "=f"(x), "=f"(y) : "l"(v));
}
__device__ __forceinline__ u64 fma2(u64 a, u64 b, u64 c){
    u64 d; asm("fma.rn.f32x2 %0, %1, %2, %3;" : "=l"(d) : "l"(a), "l"(b), "l"(c)); return d;
}
__device__ __forceinline__ u64 mul2(u64 a, u64 b){
    u64 d; asm("mul.rn.f32x2 %0, %1, %2;" : "=l"(d) : "l"(a), "l"(b)); return d;
}
__device__ __forceinline__ u64 add2(u64 a, u64 b){
    u64 d; asm("add.rn.f32x2 %0, %1, %2;" : "=l"(d) : "l"(a), "l"(b)); return d;
}
__device__ __forceinline__ u64 sh64(u64 v){
    return __shfl_xor_sync(0xffffffffu, v, 1);
}

// ---------------- K0: build QP (Q_hat, G, h) -- one block ----------------
__global__ void build_qp(const float* __restrict__ L, const float* __restrict__ LP,
                         const float* __restrict__ LR, const float* __restrict__ A,
                         const float* __restrict__ Bm, const float* __restrict__ u0,
                         const float* __restrict__ s0)
{
    __shared__ float Q[32*32], P[32*32], R[4], pw[4][64], Bh[128*NU], Ms[128*NU];
    const int t = threadIdx.x; // 256 threads

    for (int e = t; e < 1024; e += 256){
        int i = e >> 5, j = e & 31;
        int kmax = i < j ? i : j;
        float aq = (i==j) ? 1e-4f : 0.f;
        float ap = aq;
        for (int k = 0; k <= kmax; k++){
            aq = fmaf(L [i*32+k], L [j*32+k], aq);
            ap = fmaf(LP[i*32+k], LP[j*32+k], ap);
        }
        Q[e] = aq; P[e] = ap;
    }
    if (t < 4){
        int i = t >> 1, j = t & 1;
        int kmax = i < j ? i : j;
        float a = (i==j) ? 1e-4f : 0.f;
        for (int k = 0; k <= kmax; k++) a = fmaf(LR[i*2+k], LR[j*2+k], a);
        R[t] = a;
    }
    if (t < 64) pw[0][t] = Bm[t];
    __syncthreads();
    for (int s = 1; s < 4; s++){
        if (t < 64){
            int r = t >> 1, c = t & 1;
            float acc = 0.f;
            for (int k = 0; k < 32; k++) acc = fmaf(A[r*32+k], pw[s-1][k*2+c], acc);
            pw[s][t] = acc;
        }
        __syncthreads();
    }
    for (int e = t; e < 128*NU; e += 256){
        int row = e / NU, col = e - row*NU;
        int bi = row >> 5, r = row & 31, bj = col >> 1, c = col & 1;
        Bh[e] = (bj <= bi) ? pw[bi-bj][r*2+c] : 0.f;
    }
    __syncthreads();
    for (int e = t; e < 128*NU; e += 256){
        int row = e / NU, col = e - row*NU;
        int b = row >> 5, r = row & 31;
        const float* Qb = (b < 3) ? Q : P;
        float acc = 0.f;
        for (int k = 0; k < 32; k++) acc = fmaf(Qb[r*32+k], Bh[(b*32+k)*NU+col], acc);
        Ms[e] = acc;
    }
    __syncthreads();
    if (t < 100){
        int a = t / NU, b = t - (t/NU)*NU;
        float acc = ((a>>1) == (b>>1)) ? R[(a&1)*2+(b&1)] : 0.f;
        for (int row = 0; row < 128; row++) acc = fmaf(Bh[row*NU+a], Ms[row*NU+b], acc);
        g_Qhat[t] = acc;
    }
    for (int e = t; e < MI*NU; e += 256){
        int row = e / NU, col = e - (e/NU)*NU;
        g_G[e] = (row < NU) ? ((row==col) ? 1.f : 0.f) : Bh[(row-NU)*NU+col];
    }
    if (t < MI){
        float acc = s0[t];
        if (t < NU) acc += u0[t];
        else { for (int j = 0; j < NU; j++) acc = fmaf(Bh[(t-NU)*NU+j], u0[j], acc); }
        g_h[t] = acc;
    }
}

// ---------------- K1: fc1 + leaky_relu + bn1 partial stats ----------------
__global__ void __launch_bounds__(256) fc1_kernel(const float* __restrict__ x,
    const float* __restrict__ W1, const float* __restrict__ b1)
{
    __shared__ __align__(16) float xs[128*32];
    const int t = threadIdx.x;
    const int row0 = blockIdx.x * 128;
    {
        const float4* src = (const float4*)(x + row0*32);
        float4* dst = (float4*)xs;
        for (int e = t; e < 1024; e += 256) dst[e] = src[e];
    }
    __syncthreads();
    #pragma unroll
    for (int ff = 0; ff < 4; ff++){
        const int f = t + ff*256;
        float w[32];
        const float4* wp = (const float4*)(W1 + f*32);
        #pragma unroll
        for (int k = 0; k < 8; k++){
            float4 v = wp[k];
            w[4*k+0]=v.x; w[4*k+1]=v.y; w[4*k+2]=v.z; w[4*k+3]=v.w;
        }
        const float bias = b1[f];
        float sum = 0.f, sq = 0.f;
        for (int r = 0; r < 128; r++){
            float acc = bias;
            const float4* xp = (const float4*)(xs + r*32);
            #pragma unroll
            for (int k = 0; k < 8; k++){
                float4 xv = xp[k];
                acc = fmaf(xv.x, w[4*k+0], acc);
                acc = fmaf(xv.y, w[4*k+1], acc);
                acc = fmaf(xv.z, w[4*k+2], acc);
                acc = fmaf(xv.w, w[4*k+3], acc);
            }
            float v = lrelu(acc);
            g_h1[(row0+r)*NH + f] = v;
            sum += v; sq = fmaf(v, v, sq);
        }
        g_bn1p[blockIdx.x*NH + f] = sum;
        g_bn1q[blockIdx.x*NH + f] = sq;
    }
}

// ---------------- K2: bn1 finalize fused with fc2-weight fold ----------------
__global__ void fold_all(const float* __restrict__ W2, const float* __restrict__ b2,
                         const float* __restrict__ g1, const float* __restrict__ beta1)
{
    __shared__ float red[256];
    const int u = blockIdx.x, t = threadIdx.x;
    float dot = 0.f;
    for (int k = t; k < NH; k += 256){
        float sum = 0.f, sq = 0.f;
        for (int b = 0; b < FC1_BLOCKS; b++){
            sum += g_bn1p[b*NH + k];
            sq  += g_bn1q[b*NH + k];
        }
        float mu  = sum * (1.f/(float)NB);
        float var = sq  * (1.f/(float)NB) - mu*mu;
        float a = g1[k]*rsqrtf(var + 1e-5f);
        float c = beta1[k] - mu*a;
        float wv = W2[u*NH + k];
        g_W2f[u*NH + k] = wv * a;
        dot = fmaf(wv, c, dot);
    }
    red[t] = dot; __syncthreads();
    for (int s = 128; s > 0; s >>= 1){
        if (t < s) red[t] += red[t+s];
        __syncthreads();
    }
    if (t == 0) g_b2f[u] = b2[u] + red[0];
}

// ---------------- K3: fc2 (2 items per warp) + leaky_relu + bn2 stats ----------------
__global__ void __launch_bounds__(256) fc2_kernel()
{
    __shared__ float Ws[NU*NH];
    __shared__ float bs[NU];
    __shared__ float wt2[16][NU];
    const int t = threadIdx.x, lane = t & 31, wid = t >> 5;
    for (int e = t; e < NU*NH; e += 256) Ws[e] = g_W2f[e];
    if (t < NU) bs[t] = g_b2f[t];
    __syncthreads();
    const int item0 = blockIdx.x*16 + wid*2;
    float acc0[NU], acc1[NU];
    #pragma unroll
    for (int u = 0; u < NU; u++){ acc0[u] = 0.f; acc1[u] = 0.f; }
    const float* hrow0 = g_h1 + item0*NH;
    const float* hrow1 = hrow0 + NH;
    for (int j = 0; j < 32; j++){
        float hv0 = hrow0[j*32 + lane];
        float hv1 = hrow1[j*32 + lane];
        #pragma unroll
        for (int u = 0; u < NU; u++){
            float wv = Ws[u*NH + j*32 + lane];
            acc0[u] = fmaf(hv0, wv, acc0[u]);
            acc1[u] = fmaf(hv1, wv, acc1[u]);
        }
    }
    #pragma unroll
    for (int u = 0; u < NU; u++){
        #pragma unroll
        for (int off = 16; off > 0; off >>= 1){
            acc0[u] += __shfl_xor_sync(0xffffffffu, acc0[u], off);
            acc1[u] += __shfl_xor_sync(0xffffffffu, acc1[u], off);
        }
    }
    if (lane == 0){
        #pragma unroll
        for (int u = 0; u < NU; u++){
            float v0 = lrelu(acc0[u] + bs[u]);
            float v1 = lrelu(acc1[u] + bs[u]);
            g_t2[item0*NU + u] = v0;
            g_t2[(item0+1)*NU + u] = v1;
            wt2[wid*2][u] = v0;
            wt2[wid*2+1][u] = v1;
        }
    }
    __syncthreads();
    if (t < NU){
        float s = 0.f, q = 0.f;
        #pragma unroll
        for (int w = 0; w < 16; w++){ float v = wt2[w][t]; s += v; q = fmaf(v, v, q); }
        g_bn2p[blockIdx.x*NU + t] = s;
        g_bn2q[blockIdx.x*NU + t] = q;
    }
}

// ---------------- K4: finalize bn2 ----------------
__global__ void bn2_fin(const float* __restrict__ g2, const float* __restrict__ beta2)
{
    __shared__ float red[256*20];
    const int t = threadIdx.x;
    float loc[20];
    #pragma unroll
    for (int j = 0; j < 20; j++) loc[j] = 0.f;
    for (int b = t; b < FC2_BLOCKS; b += 256){
        #pragma unroll
        for (int u = 0; u < NU; u++){
            loc[u]    += g_bn2p[b*NU + u];
            loc[10+u] += g_bn2q[b*NU + u];
        }
    }
    #pragma unroll
    for (int j = 0; j < 20; j++) red[t*20 + j] = loc[j];
    __syncthreads();
    for (int s = 128; s > 0; s >>= 1){
        if (t < s){
            #pragma unroll
            for (int j = 0; j < 20; j++) red[t*20 + j] += red[(t+s)*20 + j];
        }
        __syncthreads();
    }
    if (t < NU){
        float mu  = red[t]    * (1.f/(float)NB);
        float var = red[10+t] * (1.f/(float)NB) - mu*mu;
        float a = g2[t]*rsqrtf(var + 1e-5f);
        g_bn2ac[t]      = a;
        g_bn2ac[NU + t] = beta2[t] - mu*a;
    }
}

// ---------------- K5: batched IPM, one item per THREAD PAIR ----------------
#define HOFF0 0
#define HOFF1 1
#define HOFF2 2
#define HOFF3 4
#define HOFF4 6
#define HOFF5 9
#define HOFF6 12
#define HOFF7 16
#define HOFF8 20
#define HOFF9 25

template<int K>
__device__ __forceinline__ void passA_blk(const float* __restrict__ Gblk, int sa0, int hBase,
    const u64* z2, u64* H2, u64* b1p, float smu,
    const float* s_sh, const float* l_sh, const float* h_sh)
{
    const int HOFF[10] = {HOFF0,HOFF1,HOFF2,HOFF3,HOFF4,HOFF5,HOFF6,HOFF7,HOFF8,HOFF9};
    const int KH = K/2;
    #pragma unroll 4
    for (int j = 0; j < 16; j++){
        const int sa = sa0 + j;
        float sm = s_sh[sa], lm = l_sh[sa];
        float ivs = frcp(sm);
        float w = lm*ivs;
        float2 gv[KH]; u64 g2[KH];
        #pragma unroll
        for (int jj = 0; jj < KH; jj++){
            gv[jj] = *(const float2*)&Gblk[j*K + 2*jj];
            g2[jj] = pk(gv[jj].x, gv[jj].y);
        }
        u64 acc = pk(0.f, 0.f);
        #pragma unroll
        for (int jj = 0; jj < KH; jj++) acc = fma2(g2[jj], z2[jj], acc);
        float gx, gy; upk(acc, gx, gy);
        float rp = (gx + gy) + sm - h_sh[hBase + j];
        float coef = fmaf(lm, rp, smu)*ivs;
        u64 w2v = pk(w, w), c2 = pk(coef, coef);
        u64 wgp[KH];
        #pragma unroll
        for (int jj = 0; jj < KH; jj++){
            wgp[jj] = mul2(w2v, g2[jj]);
            b1p[jj] = fma2(c2, g2[jj], b1p[jj]);
        }
        #pragma unroll
        for (int a = 0; a < K; a++){
            float ga = (a & 1) ? gv[a>>1].y : gv[a>>1].x;
            u64 ga2 = pk(ga, ga);
            #pragma unroll
            for (int pi = 0; pi <= (a>>1); pi++)
                H2[HOFF[a]+pi] = fma2(ga2, wgp[pi], H2[HOFF[a]+pi]);
        }
    }
}

template<int K>
__device__ __forceinline__ void passB1_blk(const float* __restrict__ Gblk, int sa0, int hBase,
    const u64* zpd2, float smu, float& q,
    const float* s_sh, const float* l_sh, float* r_sh, const float* h_sh)
{
    const int KH = K/2;
    #pragma unroll 4
    for (int j = 0; j < 16; j++){
        const int sa = sa0 + j;
        float sm = s_sh[sa], lm = l_sh[sa];
        u64 acc = pk(0.f, 0.f);
        #pragma unroll
        for (int jj = 0; jj < KH; jj++){
            float2 gvj = *(const float2*)&Gblk[j*K + 2*jj];
            acc = fma2(pk(gvj.x, gvj.y), zpd2[jj], acc);
        }
        float gx, gy; upk(acc, gx, gy);
        float ds = -((gx + gy) + sm - h_sh[hBase + j]);
        float rc = fmaf(sm, lm, -smu);
        float ivs = frcp(sm), ivl = frcp(lm);
        float dlam = -fmaf(lm, ds, rc)*ivs;
        q = fmaxf(q, fmaxf(-ds*ivs, -dlam*ivl));
        r_sh[sa] = ds;
    }
}

__global__ void __launch_bounds__(128, 2) ipm_kernel(float* __restrict__ out)
{
    extern __shared__ float dyn[];
    float* s_sh = dyn;                    // IPB*SROW
    float* l_sh = dyn +   IPB*SROW;
    float* r_sh = dyn + 2*IPB*SROW;
    __shared__ __align__(8) float G_sh[704];
    __shared__ float h_sh[MI];
    __shared__ __align__(8) float Q_sh[NU*NU];
    __shared__ float ac_sh[2*NU];
    const int GA[4] = {0, 80, 224, 432};
    const int GB[4] = {48, 160, 336, 576};

    const int tid = threadIdx.x;
    const int r = tid & 1, q = tid >> 1;
    const int item = blockIdx.x*IPB + q;

    // G packed: K-block bi holds rows (local j=0..31) with K=2bi+2 nonzero cols;
    // halves (j<16 / j>=16) placed 16 words apart mod 32 -> conflict-free dual broadcast
    {
        int mm = tid;  // 0..127, one structured row per thread
        int bi = mm >> 5, lr = mm & 31, hf = lr >> 4, j = lr & 15, K = 2*bi + 2;
        int base = (hf ? GB[bi] : GA[bi]) + j*K;
        for (int c = 0; c < K; c++) G_sh[base + c] = g_G[(10+mm)*NU + c];
    }
    for (int i = tid; i < MI; i += 128) h_sh[i] = g_h[i];
    if (tid < 100) Q_sh[tid] = g_Qhat[tid];
    if (tid < 20)  ac_sh[tid] = g_bn2ac[tid];
    __syncthreads();

    float z[NU], p[NU];
    u64 z2[5];
    #pragma unroll
    for (int u = 0; u < NU; u++){
        p[u] = fmaf(g_t2[item*NU+u], ac_sh[u], ac_sh[NU+u]);
        z[u] = 0.f;
    }
    #pragma unroll
    for (int j = 0; j < 5; j++) z2[j] = pk(0.f, 0.f);

    float s_id[5], l_id[5], ds_id[5];
    #pragma unroll
    for (int j = 0; j < 5; j++){ s_id[j] = 1.f; l_id[j] = 1.f; }

    // this thread's smem rows: per K-block bi, rows mm = 32*bi + 16*r + j
    int saB[4], hB[4];
    const float* Gb[4];
    #pragma unroll
    for (int bi = 0; bi < 4; bi++){
        int mm0 = 32*bi + 16*r;
        saB[bi] = q*SROW + mm0;
        hB[bi]  = 10 + mm0;
        Gb[bi]  = &G_sh[r ? GB[bi] : GA[bi]];
        #pragma unroll 4
        for (int j = 0; j < 16; j++){
            s_sh[saB[bi]+j] = 1.f; l_sh[saB[bi]+j] = 1.f;
        }
    }
    float musum = (float)MI;   // s=lam=1 initially

    for (int it = 0; it < ITER; it++){
        float smu = musum * (SIGMA/(float)MI);
        // ---- pass A: partial H2/b1p over this thread's 64 rows ----
        u64 H2[30], b1p[5];
        #pragma unroll
        for (int e = 0; e < 30; e++) H2[e] = pk(0.f, 0.f);
        #pragma unroll
        for (int j = 0; j < 5; j++) b1p[j] = pk(0.f, 0.f);

        // identity rows: compile-time indices in each parity branch (NO dynamic reg indexing)
        if (r == 0){
            #pragma unroll
            for (int j = 0; j < 5; j++){
                const int m = j;                      // 0..4 compile-time
                float sm = s_id[j], lm = l_id[j];
                float ivs = frcp(sm);
                float w = lm*ivs;
                float rp = z[m] + sm - h_sh[m];
                float c = fmaf(lm, rp, smu)*ivs;
                b1p[m/2] = add2(b1p[m/2], (m&1) ? pk(0.f,c) : pk(c,0.f));
                const int ho = (m==0?HOFF0:m==1?HOFF1:m==2?HOFF2:m==3?HOFF3:HOFF4) + m/2;
                H2[ho] = add2(H2[ho], (m&1) ? pk(0.f,w) : pk(w,0.f));
            }
        } else {
            #pragma unroll
            for (int j = 0; j < 5; j++){
                const int m = 5 + j;                  // 5..9 compile-time
                float sm = s_id[j], lm = l_id[j];
                float ivs = frcp(sm);
                float w = lm*ivs;
                float rp = z[m] + sm - h_sh[m];
                float c = fmaf(lm, rp, smu)*ivs;
                b1p[m/2] = add2(b1p[m/2], (m&1) ? pk(0.f,c) : pk(c,0.f));
                const int ho = (m==5?HOFF5:m==6?HOFF6:m==7?HOFF7:m==8?HOFF8:HOFF9) + m/2;
                H2[ho] = add2(H2[ho], (m&1) ? pk(0.f,w) : pk(w,0.f));
            }
        }

        passA_blk<2>(Gb[0], saB[0], hB[0], z2, H2, b1p, smu, s_sh, l_sh, h_sh);
        passA_blk<4>(Gb[1], saB[1], hB[1], z2, H2, b1p, smu, s_sh, l_sh, h_sh);
        passA_blk<6>(Gb[2], saB[2], hB[2], z2, H2, b1p, smu, s_sh, l_sh, h_sh);
        passA_blk<8>(Gb[3], saB[3], hB[3], z2, H2, b1p, smu, s_sh, l_sh, h_sh);

        // ---- pair combine ----
        #pragma unroll
        for (int e = 0; e < 30; e++) H2[e] = add2(H2[e], sh64(H2[e]));
        #pragma unroll
        for (int j = 0; j < 5; j++) b1p[j] = add2(b1p[j], sh64(b1p[j]));

        // ---- unpack + add Q ----
        const int HOFF[10] = {HOFF0,HOFF1,HOFF2,HOFF3,HOFF4,HOFF5,HOFF6,HOFF7,HOFF8,HOFF9};
        float Hs[55];
        #pragma unroll
        for (int a = 0; a < NU; a++){
            #pragma unroll
            for (int pi = 0; pi <= (a>>1); pi++){
                float x, y; upk(H2[HOFF[a]+pi], x, y);
                Hs[(a*(a+1))/2 + 2*pi] = x + Q_sh[a*NU + 2*pi];
                if (2*pi+1 <= a) Hs[(a*(a+1))/2 + 2*pi+1] = y + Q_sh[a*NU + 2*pi+1];
            }
        }
        float b1[NU];
        #pragma unroll
        for (int j = 0; j < 5; j++) upk(b1p[j], b1[2*j], b1[2*j+1]);

        // ---- rhs (in place -> dz) ----
        float dz[NU];
        #pragma unroll
        for (int i = 0; i < NU; i++){
            u64 acc = pk(0.f, 0.f);
            #pragma unroll
            for (int j = 0; j < 5; j++){
                float2 qv = *(const float2*)&Q_sh[i*NU + 2*j];
                acc = fma2(pk(qv.x, qv.y), z2[j], acc);
            }
            float qx, qy; upk(acc, qx, qy);
            dz[i] = -(p[i] + b1[i] + qx + qy);
        }
        // ---- Cholesky (duplicated in both threads) ----
        #pragma unroll
        for (int k = 0; k < NU; k++){
            float inv = rsqrtf(Hs[(k*(k+1))/2+k]);
            Hs[(k*(k+1))/2+k] = inv;
            #pragma unroll
            for (int i = k+1; i < NU; i++) Hs[(i*(i+1))/2+k] *= inv;
            #pragma unroll
            for (int j = k+1; j < NU; j++){
                float ljk = Hs[(j*(j+1))/2+k];
                #pragma unroll
                for (int i = j; i < NU; i++)
                    Hs[(i*(i+1))/2+j] = fmaf(-Hs[(i*(i+1))/2+k], ljk, Hs[(i*(i+1))/2+j]);
            }
        }
        #pragma unroll
        for (int i = 0; i < NU; i++){
            float tt = dz[i];
            #pragma unroll
            for (int j = 0; j < i; j++) tt = fmaf(-Hs[(i*(i+1))/2+j], dz[j], tt);
            dz[i] = tt * Hs[(i*(i+1))/2+i];
        }
        #pragma unroll
        for (int i = NU-1; i >= 0; i--){
            float tt = dz[i];
            #pragma unroll
            for (int j = i+1; j < NU; j++) tt = fmaf(-Hs[(j*(j+1))/2+i], dz[j], tt);
            dz[i] = tt * Hs[(i*(i+1))/2+i];
        }
        u64 dz2[5], zpd2[5];
        #pragma unroll
        for (int j = 0; j < 5; j++){
            dz2[j] = pk(dz[2*j], dz[2*j+1]);
            zpd2[j] = add2(z2[j], dz2[j]);
        }

        // ---- pass B1: step-length ratios (ds from G·(z+dz)) ----
        float qm = 0.f;
        if (r == 0){
            #pragma unroll
            for (int j = 0; j < 5; j++){
                const int m = j;
                float sm = s_id[j], lm = l_id[j];
                float ds = -((z[m] + dz[m]) + sm - h_sh[m]);
                float rc = fmaf(sm, lm, -smu);
                float ivs = frcp(sm), ivl = frcp(lm);
                float dlam = -fmaf(lm, ds, rc)*ivs;
                qm = fmaxf(qm, fmaxf(-ds*ivs, -dlam*ivl));
                ds_id[j] = ds;
            }
        } else {
            #pragma unroll
            for (int j = 0; j < 5; j++){
                const int m = 5 + j;
                float sm = s_id[j], lm = l_id[j];
                float ds = -((z[m] + dz[m]) + sm - h_sh[m]);
                float rc = fmaf(sm, lm, -smu);
                float ivs = frcp(sm), ivl = frcp(lm);
                float dlam = -fmaf(lm, ds, rc)*ivs;
                qm = fmaxf(qm, fmaxf(-ds*ivs, -dlam*ivl));
                ds_id[j] = ds;
            }
        }
        passB1_blk<2>(Gb[0], saB[0], hB[0], zpd2, smu, qm, s_sh, l_sh, r_sh, h_sh);
        passB1_blk<4>(Gb[1], saB[1], hB[1], zpd2, smu, qm, s_sh, l_sh, r_sh, h_sh);
        passB1_blk<6>(Gb[2], saB[2], hB[2], zpd2, smu, qm, s_sh, l_sh, r_sh, h_sh);
        passB1_blk<8>(Gb[3], saB[3], hB[3], zpd2, smu, qm, s_sh, l_sh, r_sh, h_sh);
        qm = fmaxf(qm, __shfl_xor_sync(0xffffffffu, qm, 1));
        float alpha = fminf(1.f, 0.99f*frcp(qm));

        // ---- pass B2: update s, lam; accumulate next-iter musum ----
        float msn = 0.f;
        #pragma unroll
        for (int j = 0; j < 5; j++){             // identity rows (j-indexed state only)
            float sm = s_id[j], lm = l_id[j];
            float ds = ds_id[j];
            float rc = fmaf(sm, lm, -smu);
            float ivs = frcp(sm);
            float dlam = -fmaf(lm, ds, rc)*ivs;
            float sn = fmaf(alpha, ds, sm);
            float ln = fmaf(alpha, dlam, lm);
            s_id[j] = sn; l_id[j] = ln;
            msn = fmaf(sn, ln, msn);
        }
        #pragma unroll
        for (int bi = 0; bi < 4; bi++){
            #pragma unroll 4
            for (int j = 0; j < 16; j++){
                const int sa = saB[bi] + j;
                float sm = s_sh[sa], lm = l_sh[sa];
                float ds = r_sh[sa];
                float rc = fmaf(sm, lm, -smu);
                float ivs = frcp(sm);
                float dlam = -fmaf(lm, ds, rc)*ivs;
                float sn = fmaf(alpha, ds, sm);
                float ln = fmaf(alpha, dlam, lm);
                s_sh[sa] = sn; l_sh[sa] = ln;
                msn = fmaf(sn, ln, msn);
            }
        }
        msn += __shfl_xor_sync(0xffffffffu, msn, 1);
        musum = msn;

        #pragma unroll
        for (int u = 0; u < NU; u++) z[u] = fmaf(alpha, dz[u], z[u]);
        #pragma unroll
        for (int j = 0; j < 5; j++) z2[j] = pk(z[2*j], z[2*j+1]);
    }
    if (r == 0) out[item] = z[0];
}

// ---------------- launch ----------------
extern "C" void kernel_launch(void* const* d_in, const int* in_sizes, int n_in,
                              void* d_out, int out_size)
{
    (void)in_sizes; (void)n_in; (void)out_size;
    const float* x    = (const float*)d_in[0];
    const float* w1   = (const float*)d_in[1];
    const float* b1   = (const float*)d_in[2];
    const float* w2   = (const float*)d_in[3];
    const float* b2   = (const float*)d_in[4];
    const float* bn1g = (const float*)d_in[5];
    const float* bn1b = (const float*)d_in[6];
    const float* bn2g = (const float*)d_in[7];
    const float* bn2b = (const float*)d_in[8];
    const float* L    = (const float*)d_in[9];
    const float* LP   = (const float*)d_in[10];
    const float* LR   = (const float*)d_in[11];
    const float* A    = (const float*)d_in[12];
    const float* Bm   = (const float*)d_in[13];
    const float* u0   = (const float*)d_in[14];
    const float* s0   = (const float*)d_in[15];
    float* out = (float*)d_out;

    const int ipm_smem = 3*IPB*SROW*(int)sizeof(float);   // 99,072 B -> 2 blocks/SM
    cudaFuncSetAttribute(ipm_kernel, cudaFuncAttributeMaxDynamicSharedMemorySize, ipm_smem);

    build_qp<<<1, 256>>>(L, LP, LR, A, Bm, u0, s0);
    fc1_kernel<<<FC1_BLOCKS, 256>>>(x, w1, b1);
    fold_all<<<NU, 256>>>(w2, b2, bn1g, bn1b);
    fc2_kernel<<<FC2_BLOCKS, 256>>>();
    bn2_fin<<<1, 256>>>(bn2g, bn2b);
    ipm_kernel<<<NB/IPB, 128, ipm_smem>>>(out);
}